// round 7
// baseline (speedup 1.0000x reference)
#include <cuda_runtime.h>
#include <cstdint>
#include <math.h>

#define TB 8192      // tokens = B*S
#define HD 1024
#define NE 8
#define FF 4096

// GEMM tiling: CTA 256x128, 8 warps (4x2), warptile 64x64
#define GT 256       // GEMM threads per CTA
#define BM 256
#define BN 128
#define KC 32
#define STAGES 3
#define ASTRIDE 36   // floats; frag-read bank = 4*lr + lc  (conflict-free)
#define BSTRIDE 136  // floats (128 data + 8 pad); frag-read bank = 8*lc + lr (conflict-free)

#define A_STG_F (BM * ASTRIDE)            // 9216 floats
#define B_STG_F (KC * BSTRIDE)            // 4352 floats
#define A_BYTES (STAGES * A_STG_F * 4)    // 110592
#define B_BYTES (STAGES * B_STG_F * 4)    // 52224
#define SMEM_SZ (A_BYTES + B_BYTES + 4096) // ~167KB -> 1 CTA/SM, 8 warps

// ---- scratch (static device arrays; no allocation) ----
__device__ float g_x [(size_t)TB * HD];        // tf32-rounded x (written by router)
__device__ float g_w1[(size_t)NE * HD * FF];   // tf32-rounded W1
__device__ float g_w2[(size_t)NE * FF * HD];   // tf32-rounded W2
__device__ float g_h [(size_t)2 * TB * FF];    // gelu(x@W1) per slot (tf32-rounded)
__device__ float g_y [(size_t)2 * TB * HD];    // h@W2 per slot
__device__ int   g_cnt[NE];
__device__ int   g_tok[NE * TB];
__device__ int   g_slot[NE * TB];
__device__ int   g_eid[2 * TB];
__device__ float g_p0[TB];

// ---- helpers ----
__device__ __forceinline__ uint32_t smem_u32(const void* p) {
    uint32_t a;
    asm("{ .reg .u64 t; cvta.to.shared.u64 t, %1; cvt.u32.u64 %0, t; }" : "=r"(a) : "l"(p));
    return a;
}
__device__ __forceinline__ uint32_t f2tf32(float x) {
    uint32_t u;
    asm("cvt.rna.tf32.f32 %0, %1;" : "=r"(u) : "f"(x));
    return u;
}
__device__ __forceinline__ void cp16(uint32_t s, const void* g) {
    asm volatile("cp.async.cg.shared.global [%0], [%1], 16;" :: "r"(s), "l"(g));
}
#define CP_COMMIT() asm volatile("cp.async.commit_group;" ::: "memory")
#define CP_WAIT2()  asm volatile("cp.async.wait_group 2;" ::: "memory")

#define MMA_TF32(d, a, b) \
    asm volatile("mma.sync.aligned.m16n8k8.row.col.f32.tf32.tf32.f32 " \
        "{%0,%1,%2,%3}, {%4,%5,%6,%7}, {%8,%9}, {%0,%1,%2,%3};" \
        : "+f"((d)[0]), "+f"((d)[1]), "+f"((d)[2]), "+f"((d)[3]) \
        : "r"((a)[0]), "r"((a)[1]), "r"((a)[2]), "r"((a)[3]), \
          "r"((b)[0]), "r"((b)[1]))

__device__ __forceinline__ float fgelu(float v) {
    float z = 0.7978845608028654f * (v + 0.044715f * v * v * v);
    float e = __expf(2.0f * z);
    float t = 1.0f - 2.0f / (e + 1.0f);   // tanh(z)
    return 0.5f * v * (1.0f + t);
}

// ---------------------------------------------------------------------------
__global__ void k_init() {
    if (threadIdx.x < NE) g_cnt[threadIdx.x] = 0;
}

// tf32-round a tensor (float4 grid-stride)
__global__ void k_cvt(const float* __restrict__ src, float* __restrict__ dst, int n4) {
    int i = blockIdx.x * blockDim.x + threadIdx.x;
    for (int j = i; j < n4; j += gridDim.x * blockDim.x) {
        float4 v = ((const float4*)src)[j];
        uint4 u;
        u.x = f2tf32(v.x); u.y = f2tf32(v.y);
        u.z = f2tf32(v.z); u.w = f2tf32(v.w);
        ((uint4*)dst)[j] = u;
    }
}

// ---------------------------------------------------------------------------
// Router (also writes tf32-rounded x into g_x)
// ---------------------------------------------------------------------------
__global__ void k_router(const float* __restrict__ x,
                         const float* __restrict__ Wr,
                         const float* __restrict__ br) {
    int warp = (blockIdx.x * blockDim.x + threadIdx.x) >> 5;
    int lane = threadIdx.x & 31;
    if (warp >= TB) return;
    const float* xr = x + (size_t)warp * HD;
    uint32_t* gxr = (uint32_t*)g_x + (size_t)warp * HD;

    float acc[NE];
#pragma unroll
    for (int e = 0; e < NE; e++) acc[e] = 0.f;
    for (int h = lane; h < HD; h += 32) {
        float xv = xr[h];
        gxr[h] = f2tf32(xv);
        float4 w0 = *(const float4*)(Wr + h * NE);
        float4 w1 = *(const float4*)(Wr + h * NE + 4);
        acc[0] += xv * w0.x; acc[1] += xv * w0.y;
        acc[2] += xv * w0.z; acc[3] += xv * w0.w;
        acc[4] += xv * w1.x; acc[5] += xv * w1.y;
        acc[6] += xv * w1.z; acc[7] += xv * w1.w;
    }
#pragma unroll
    for (int e = 0; e < NE; e++)
#pragma unroll
        for (int off = 16; off > 0; off >>= 1)
            acc[e] += __shfl_xor_sync(0xffffffffu, acc[e], off);
    if (lane == 0) {
#pragma unroll
        for (int e = 0; e < NE; e++) acc[e] += br[e];
        int i1 = 0; float l1 = acc[0];
#pragma unroll
        for (int e = 1; e < NE; e++) if (acc[e] > l1) { l1 = acc[e]; i1 = e; }
        int i2 = -1; float l2 = -3.0e38f;
#pragma unroll
        for (int e = 0; e < NE; e++) if (e != i1 && acc[e] > l2) { l2 = acc[e]; i2 = e; }
        g_p0[warp] = 1.0f / (1.0f + expf(l2 - l1));
        g_eid[2 * warp]     = i1;
        g_eid[2 * warp + 1] = i2;
        int p = atomicAdd(&g_cnt[i1], 1);
        g_tok[i1 * TB + p]  = warp;
        g_slot[i1 * TB + p] = 2 * warp;
        p = atomicAdd(&g_cnt[i2], 1);
        g_tok[i2 * TB + p]  = warp;
        g_slot[i2 * TB + p] = 2 * warp + 1;
    }
}

// ---------------------------------------------------------------------------
// Grouped GEMM on mma.sync tf32. 256 threads, 8 warps (4x2), warptile 64x64.
// MODE 0: g_h[slot] = tf32(gelu(x[tok] @ W1[e] + b1[e]))   (K=HD, N over FF)
// MODE 1: g_y[slot] = g_h[slot] @ W2[e]                    (K=FF, N over HD)
// ---------------------------------------------------------------------------
template <int MODE>
__global__ __launch_bounds__(GT, 1)
void k_gemm(const float* __restrict__ bias) {
    constexpr int KTOT = MODE ? FF : HD;
    constexpr int LDA  = MODE ? FF : HD;
    constexpr int WROW = MODE ? HD : FF;
    constexpr int OROW = MODE ? HD : FF;
    constexpr int NC   = KTOT / KC;

    const int e  = blockIdx.z;
    const int me = g_cnt[e];
    const int mt = blockIdx.y;
    if (mt * BM >= me) return;
    const int ntb = blockIdx.x * BN;

    extern __shared__ char smraw[];
    float* As = (float*)smraw;
    float* Bs = (float*)(smraw + A_BYTES);
    int* stok  = (int*)(smraw + A_BYTES + B_BYTES);
    int* sslot = stok + BM;

    const int tid  = threadIdx.x;
    const int wid  = tid >> 5;
    const int lane = tid & 31;
    const int wm   = wid >> 1;       // 0..3
    const int wn   = wid & 1;        // 0..1
    const int lr   = lane >> 2;      // 0..7  (groupID)
    const int lc   = lane & 3;       // 0..3  (threadID_in_group)

    // token/slot lists (256 rows, 256 threads)
    {
        int i = mt * BM + tid;
        int tok = 0, slot = -1;
        if (i < me) { tok = g_tok[e * TB + i]; slot = g_slot[e * TB + i]; }
        stok[tid] = tok; sslot[tid] = slot;
    }
    __syncthreads();

    // ---- cp.async mappings ----
    // A: row = (tid>>3) + 32*m  (m=0..7), col float4 = tid&7.
    //    Per warp: 4 rows x 128B contiguous (full sectors).
    const float* Asrc = MODE ? (const float*)g_h : (const float*)g_x;
    const float* aptr[8];
#pragma unroll
    for (int m = 0; m < 8; m++) {
        int row = (tid >> 3) + 32 * m;
        int rid = MODE ? sslot[row] : stok[row];
        if (rid < 0) rid = 0;
        aptr[m] = Asrc + (size_t)rid * LDA + (tid & 7) * 4;
    }
    const uint32_t asmA = smem_u32(As) +
        (uint32_t)((tid >> 3) * ASTRIDE + (tid & 7) * 4) * 4;

    // B: k-row = tid>>3 (0..31), col floats = (tid&7)*4 + 32*m (m=0..3).
    //    Per (row,m): 8 lanes cover 128B contiguous.
    const int bkr = tid >> 3;
    const float* Wsrc = MODE ? (const float*)g_w2 : (const float*)g_w1;
    const float* bglob = Wsrc + (size_t)e * HD * FF + (size_t)bkr * WROW + ntb + (tid & 7) * 4;
    const uint32_t bsmB = smem_u32(Bs) +
        (uint32_t)(bkr * BSTRIDE + (tid & 7) * 4) * 4;

#define LOAD_CHUNK(STG, C)                                                    \
    {                                                                         \
        uint32_t as_ = asmA + (STG) * (A_STG_F * 4);                          \
        _Pragma("unroll")                                                     \
        for (int m = 0; m < 8; m++)                                           \
            cp16(as_ + m * (32 * ASTRIDE * 4), aptr[m] + (C) * KC);           \
        const float* bg = bglob + (size_t)(C) * KC * WROW;                    \
        uint32_t bs_ = bsmB + (STG) * (B_STG_F * 4);                          \
        _Pragma("unroll")                                                     \
        for (int m = 0; m < 4; m++)                                           \
            cp16(bs_ + m * 128, bg + m * 32);                                 \
    }

    float acc[4][8][4];
#pragma unroll
    for (int i = 0; i < 4; i++)
#pragma unroll
        for (int j = 0; j < 8; j++)
#pragma unroll
            for (int r = 0; r < 4; r++) acc[i][j][r] = 0.f;

    LOAD_CHUNK(0, 0); CP_COMMIT();
    LOAD_CHUNK(1, 1); CP_COMMIT();

    const uint32_t* Au0 = (const uint32_t*)As + (wm * 64 + lr) * ASTRIDE + lc;
    const uint32_t* Bu0 = (const uint32_t*)Bs + lc * BSTRIDE + wn * 64 + lr;

    for (int c = 0; c < NC; c++) {
        const int pf = c + STAGES - 1;
        if (pf < NC) { LOAD_CHUNK(pf % STAGES, pf); }
        CP_COMMIT();
        CP_WAIT2();
        __syncthreads();

        const int st = c % STAGES;
        const uint32_t* Au = Au0 + st * A_STG_F;
        const uint32_t* Bu = Bu0 + st * B_STG_F;
#pragma unroll
        for (int k8 = 0; k8 < KC / 8; k8++) {
            const int ck = k8 * 8;
            uint32_t af[4][4], bf[8][2];
#pragma unroll
            for (int i = 0; i < 4; i++) {
                af[i][0] = Au[(16 * i) * ASTRIDE + ck];
                af[i][1] = Au[(16 * i + 8) * ASTRIDE + ck];
                af[i][2] = Au[(16 * i) * ASTRIDE + ck + 4];
                af[i][3] = Au[(16 * i + 8) * ASTRIDE + ck + 4];
            }
#pragma unroll
            for (int j = 0; j < 8; j++) {
                bf[j][0] = Bu[ck * BSTRIDE + 8 * j];
                bf[j][1] = Bu[(ck + 4) * BSTRIDE + 8 * j];
            }
#pragma unroll
            for (int i = 0; i < 4; i++)
#pragma unroll
                for (int j = 0; j < 8; j++)
                    MMA_TF32(acc[i][j], af[i], bf[j]);
        }
        __syncthreads();
    }

    // ---- epilogue ----
    float* outbase = MODE ? (float*)g_y : (float*)g_h;

    float bv[16];
    if (MODE == 0) {
#pragma unroll
        for (int j = 0; j < 8; j++) {
            float2 t = *(const float2*)(bias + e * FF + ntb + wn * 64 + 8 * j + lc * 2);
            bv[2 * j] = t.x; bv[2 * j + 1] = t.y;
        }
    }

#pragma unroll
    for (int i = 0; i < 4; i++) {
        const int mr0 = wm * 64 + 16 * i + lr;
        const int s0 = sslot[mr0];
        const int s1 = sslot[mr0 + 8];
#pragma unroll
        for (int j = 0; j < 8; j++) {
            const int n = ntb + wn * 64 + 8 * j + lc * 2;
            if (MODE == 0) {
                if (s0 >= 0) {
                    float2 v;
                    v.x = __uint_as_float(f2tf32(fgelu(acc[i][j][0] + bv[2 * j])));
                    v.y = __uint_as_float(f2tf32(fgelu(acc[i][j][1] + bv[2 * j + 1])));
                    *(float2*)(outbase + (size_t)s0 * OROW + n) = v;
                }
                if (s1 >= 0) {
                    float2 v;
                    v.x = __uint_as_float(f2tf32(fgelu(acc[i][j][2] + bv[2 * j])));
                    v.y = __uint_as_float(f2tf32(fgelu(acc[i][j][3] + bv[2 * j + 1])));
                    *(float2*)(outbase + (size_t)s1 * OROW + n) = v;
                }
            } else {
                if (s0 >= 0)
                    *(float2*)(outbase + (size_t)s0 * OROW + n) =
                        make_float2(acc[i][j][0], acc[i][j][1]);
                if (s1 >= 0)
                    *(float2*)(outbase + (size_t)s1 * OROW + n) =
                        make_float2(acc[i][j][2], acc[i][j][3]);
            }
        }
    }
}

// ---------------------------------------------------------------------------
// out[t] = p0[t] * (y[2t] + y[2t+1] + b2[e0] + b2[e1])
// ---------------------------------------------------------------------------
__global__ void k_combine(const float* __restrict__ b2, float* __restrict__ out) {
    int idx = blockIdx.x * blockDim.x + threadIdx.x;   // over TB*HD/4
    int tok = idx >> 8;       // HD/4 = 256
    int h4  = idx & 255;
    int e0 = g_eid[2 * tok], e1 = g_eid[2 * tok + 1];
    float p0 = g_p0[tok];
    float4 y0 = ((const float4*)g_y)[(size_t)(2 * tok) * 256 + h4];
    float4 y1 = ((const float4*)g_y)[(size_t)(2 * tok + 1) * 256 + h4];
    float4 c0 = *(const float4*)(b2 + e0 * HD + 4 * h4);
    float4 c1 = *(const float4*)(b2 + e1 * HD + 4 * h4);
    float4 o;
    o.x = p0 * (y0.x + y1.x + c0.x + c1.x);
    o.y = p0 * (y0.y + y1.y + c0.y + c1.y);
    o.z = p0 * (y0.z + y1.z + c0.z + c1.z);
    o.w = p0 * (y0.w + y1.w + c0.w + c1.w);
    ((float4*)out)[idx] = o;
}

// ---------------------------------------------------------------------------
extern "C" void kernel_launch(void* const* d_in, const int* in_sizes, int n_in,
                              void* d_out, int out_size) {
    const float* x  = (const float*)d_in[0];
    const float* Wr = (const float*)d_in[1];
    const float* br = (const float*)d_in[2];
    const float* W1 = (const float*)d_in[3];
    const float* b1 = (const float*)d_in[4];
    const float* W2 = (const float*)d_in[5];
    const float* b2 = (const float*)d_in[6];
    float* out = (float*)d_out;

    cudaFuncSetAttribute(k_gemm<0>, cudaFuncAttributeMaxDynamicSharedMemorySize, SMEM_SZ);
    cudaFuncSetAttribute(k_gemm<1>, cudaFuncAttributeMaxDynamicSharedMemorySize, SMEM_SZ);

    float* gw1; cudaGetSymbolAddress((void**)&gw1, g_w1);
    float* gw2; cudaGetSymbolAddress((void**)&gw2, g_w2);

    k_init<<<1, 32>>>();
    k_router<<<TB / 8, 256>>>(x, Wr, br);
    k_cvt<<<8192, 256>>>(W1, gw1, NE * HD * FF / 4);
    k_cvt<<<8192, 256>>>(W2, gw2, NE * FF * HD / 4);
    dim3 g1(FF / BN, TB / BM, NE);   // (32, 32, 8)
    k_gemm<0><<<g1, GT, SMEM_SZ>>>(b1);
    dim3 g2(HD / BN, TB / BM, NE);   // (8, 32, 8)
    k_gemm<1><<<g2, GT, SMEM_SZ>>>(nullptr);
    k_combine<<<TB * HD / 4 / 256, 256>>>(b2, out);
}

// round 8
// speedup vs baseline: 1.2053x; 1.2053x over previous
#include <cuda_runtime.h>
#include <cstdint>
#include <math.h>

#define TB 8192      // tokens = B*S
#define HD 1024
#define NE 8
#define FF 4096

// GEMM tiling: CTA 128x128, 4 warps (2x2), warptile 64x64  (R6 winner)
#define GT 128       // GEMM threads per CTA
#define BM 128
#define BN 128
#define KC 32
#define STAGES 3
#define ASTRIDE 36   // floats; frag-read bank = 4*lr + lc  (conflict-free)
#define BSTRIDE 136  // floats (128 data + 8 pad); frag-read bank = 8*lc + lr (conflict-free)

#define A_STG_F (BM * ASTRIDE)            // 4608 floats
#define B_STG_F (KC * BSTRIDE)            // 4352 floats
#define A_BYTES (STAGES * A_STG_F * 4)    // 55296
#define B_BYTES (STAGES * B_STG_F * 4)    // 52224
#define SMEM_SZ (A_BYTES + B_BYTES + 1024) // 108544 -> 2 CTA/SM

// ---- scratch (static device arrays; no allocation) ----
__device__ float g_x [(size_t)TB * HD];        // tf32-rounded x (written by router)
__device__ float g_h [(size_t)2 * TB * FF];    // gelu(x@W1) per slot (tf32-rounded)
__device__ float g_y [(size_t)2 * TB * HD];    // h@W2 per slot
__device__ int   g_cnt[NE];
__device__ int   g_tok[NE * TB];
__device__ int   g_slot[NE * TB];
__device__ int   g_eid[2 * TB];
__device__ float g_p0[TB];

// ---- helpers ----
__device__ __forceinline__ uint32_t smem_u32(const void* p) {
    uint32_t a;
    asm("{ .reg .u64 t; cvta.to.shared.u64 t, %1; cvt.u32.u64 %0, t; }" : "=r"(a) : "l"(p));
    return a;
}
__device__ __forceinline__ uint32_t f2tf32(float x) {
    uint32_t u;
    asm("cvt.rna.tf32.f32 %0, %1;" : "=r"(u) : "f"(x));
    return u;
}
__device__ __forceinline__ void cp16(uint32_t s, const void* g) {
    asm volatile("cp.async.cg.shared.global [%0], [%1], 16;" :: "r"(s), "l"(g));
}
#define CP_COMMIT() asm volatile("cp.async.commit_group;" ::: "memory")
#define CP_WAIT2()  asm volatile("cp.async.wait_group 2;" ::: "memory")

#define MMA_TF32(d, a, b) \
    asm volatile("mma.sync.aligned.m16n8k8.row.col.f32.tf32.tf32.f32 " \
        "{%0,%1,%2,%3}, {%4,%5,%6,%7}, {%8,%9}, {%0,%1,%2,%3};" \
        : "+f"((d)[0]), "+f"((d)[1]), "+f"((d)[2]), "+f"((d)[3]) \
        : "r"((a)[0]), "r"((a)[1]), "r"((a)[2]), "r"((a)[3]), \
          "r"((b)[0]), "r"((b)[1]))

__device__ __forceinline__ float fgelu(float v) {
    float z = 0.7978845608028654f * (v + 0.044715f * v * v * v);
    float e = __expf(2.0f * z);
    float t = 1.0f - 2.0f / (e + 1.0f);   // tanh(z)
    return 0.5f * v * (1.0f + t);
}

// ---------------------------------------------------------------------------
__global__ void k_init() {
    if (threadIdx.x < NE) g_cnt[threadIdx.x] = 0;
}

// ---------------------------------------------------------------------------
// Router (also writes tf32-rounded x into g_x)
// ---------------------------------------------------------------------------
__global__ void k_router(const float* __restrict__ x,
                         const float* __restrict__ Wr,
                         const float* __restrict__ br) {
    int warp = (blockIdx.x * blockDim.x + threadIdx.x) >> 5;
    int lane = threadIdx.x & 31;
    if (warp >= TB) return;
    const float* xr = x + (size_t)warp * HD;
    uint32_t* gxr = (uint32_t*)g_x + (size_t)warp * HD;

    float acc[NE];
#pragma unroll
    for (int e = 0; e < NE; e++) acc[e] = 0.f;
    for (int h = lane; h < HD; h += 32) {
        float xv = xr[h];
        gxr[h] = f2tf32(xv);
        float4 w0 = *(const float4*)(Wr + h * NE);
        float4 w1 = *(const float4*)(Wr + h * NE + 4);
        acc[0] += xv * w0.x; acc[1] += xv * w0.y;
        acc[2] += xv * w0.z; acc[3] += xv * w0.w;
        acc[4] += xv * w1.x; acc[5] += xv * w1.y;
        acc[6] += xv * w1.z; acc[7] += xv * w1.w;
    }
#pragma unroll
    for (int e = 0; e < NE; e++)
#pragma unroll
        for (int off = 16; off > 0; off >>= 1)
            acc[e] += __shfl_xor_sync(0xffffffffu, acc[e], off);
    if (lane == 0) {
#pragma unroll
        for (int e = 0; e < NE; e++) acc[e] += br[e];
        int i1 = 0; float l1 = acc[0];
#pragma unroll
        for (int e = 1; e < NE; e++) if (acc[e] > l1) { l1 = acc[e]; i1 = e; }
        int i2 = -1; float l2 = -3.0e38f;
#pragma unroll
        for (int e = 0; e < NE; e++) if (e != i1 && acc[e] > l2) { l2 = acc[e]; i2 = e; }
        g_p0[warp] = 1.0f / (1.0f + expf(l2 - l1));
        g_eid[2 * warp]     = i1;
        g_eid[2 * warp + 1] = i2;
        int p = atomicAdd(&g_cnt[i1], 1);
        g_tok[i1 * TB + p]  = warp;
        g_slot[i1 * TB + p] = 2 * warp;
        p = atomicAdd(&g_cnt[i2], 1);
        g_tok[i2 * TB + p]  = warp;
        g_slot[i2 * TB + p] = 2 * warp + 1;
    }
}

// ---------------------------------------------------------------------------
// Grouped GEMM on mma.sync tf32. 128 threads, 4 warps (2x2), warptile 64x64.
// B operand = raw fp32 weights; mma truncates to tf32 in-register (no cvt pass).
// MODE 0: g_h[slot] = tf32(gelu(x[tok] @ W1[e] + b1[e]))   (K=HD, N over FF)
// MODE 1: g_y[slot] = g_h[slot] @ W2[e]                    (K=FF, N over HD)
// ---------------------------------------------------------------------------
template <int MODE>
__global__ __launch_bounds__(GT, 2)
void k_gemm(const float* __restrict__ W, const float* __restrict__ bias) {
    constexpr int KTOT = MODE ? FF : HD;
    constexpr int LDA  = MODE ? FF : HD;
    constexpr int WROW = MODE ? HD : FF;
    constexpr int OROW = MODE ? HD : FF;
    constexpr int NC   = KTOT / KC;

    const int e  = blockIdx.z;
    const int me = g_cnt[e];
    const int mt = blockIdx.y;
    if (mt * BM >= me) return;
    const int ntb = blockIdx.x * BN;

    extern __shared__ char smraw[];
    float* As = (float*)smraw;
    float* Bs = (float*)(smraw + A_BYTES);
    int* stok  = (int*)(smraw + A_BYTES + B_BYTES);
    int* sslot = stok + 128;

    const int tid  = threadIdx.x;
    const int wid  = tid >> 5;
    const int lane = tid & 31;
    const int wm   = wid >> 1;       // 0..1
    const int wn   = wid & 1;        // 0..1
    const int lr   = lane >> 2;      // 0..7  (groupID)
    const int lc   = lane & 3;       // 0..3  (threadID_in_group)

    // token/slot lists (128 rows, 128 threads)
    {
        int i = mt * BM + tid;
        int tok = 0, slot = -1;
        if (i < me) { tok = g_tok[e * TB + i]; slot = g_slot[e * TB + i]; }
        stok[tid] = tok; sslot[tid] = slot;
    }
    __syncthreads();

    // ---- cp.async mappings ----
    // A: row = (tid>>3) + 16*m  (m=0..7), col float4 = tid&7. Per m, a warp
    //    covers 4 rows x 128B contiguous (full sectors).
    const float* Asrc = MODE ? (const float*)g_h : (const float*)g_x;
    const float* aptr[8];
#pragma unroll
    for (int m = 0; m < 8; m++) {
        int row = (tid >> 3) + 16 * m;
        int rid = MODE ? sslot[row] : stok[row];
        if (rid < 0) rid = 0;
        aptr[m] = Asrc + (size_t)rid * LDA + (tid & 7) * 4;
    }
    const uint32_t asmA = smem_u32(As) +
        (uint32_t)((tid >> 3) * ASTRIDE + (tid & 7) * 4) * 4;

    // B: k-row = tid>>2, col floats = (tid&3)*4 + 16*m. Per (row,m) 4 lanes
    //    cover 64B contiguous.
    const int bkr = tid >> 2;
    const float* bglob = W + (size_t)e * HD * FF + (size_t)bkr * WROW + ntb + (tid & 3) * 4;
    const uint32_t bsmB = smem_u32(Bs) +
        (uint32_t)(bkr * BSTRIDE + (tid & 3) * 4) * 4;

#define LOAD_CHUNK(STG, C)                                                    \
    {                                                                         \
        uint32_t as_ = asmA + (STG) * (A_STG_F * 4);                          \
        _Pragma("unroll")                                                     \
        for (int m = 0; m < 8; m++)                                           \
            cp16(as_ + m * (16 * ASTRIDE * 4), aptr[m] + (C) * KC);           \
        const float* bg = bglob + (size_t)(C) * KC * WROW;                    \
        uint32_t bs_ = bsmB + (STG) * (B_STG_F * 4);                          \
        _Pragma("unroll")                                                     \
        for (int m = 0; m < 8; m++)                                           \
            cp16(bs_ + m * 64, bg + m * 16);                                  \
    }

    float acc[4][8][4];
#pragma unroll
    for (int i = 0; i < 4; i++)
#pragma unroll
        for (int j = 0; j < 8; j++)
#pragma unroll
            for (int r = 0; r < 4; r++) acc[i][j][r] = 0.f;

    LOAD_CHUNK(0, 0); CP_COMMIT();
    LOAD_CHUNK(1, 1); CP_COMMIT();

    const uint32_t* Au0 = (const uint32_t*)As + (wm * 64 + lr) * ASTRIDE + lc;
    const uint32_t* Bu0 = (const uint32_t*)Bs + lc * BSTRIDE + wn * 64 + lr;

    for (int c = 0; c < NC; c++) {
        const int pf = c + STAGES - 1;
        if (pf < NC) { LOAD_CHUNK(pf % STAGES, pf); }
        CP_COMMIT();
        CP_WAIT2();
        __syncthreads();

        const int st = c % STAGES;
        const uint32_t* Au = Au0 + st * A_STG_F;
        const uint32_t* Bu = Bu0 + st * B_STG_F;
#pragma unroll
        for (int k8 = 0; k8 < KC / 8; k8++) {
            const int ck = k8 * 8;
            uint32_t af[4][4], bf[8][2];
#pragma unroll
            for (int i = 0; i < 4; i++) {
                af[i][0] = Au[(16 * i) * ASTRIDE + ck];
                af[i][1] = Au[(16 * i + 8) * ASTRIDE + ck];
                af[i][2] = Au[(16 * i) * ASTRIDE + ck + 4];
                af[i][3] = Au[(16 * i + 8) * ASTRIDE + ck + 4];
            }
#pragma unroll
            for (int j = 0; j < 8; j++) {
                bf[j][0] = Bu[ck * BSTRIDE + 8 * j];
                bf[j][1] = Bu[(ck + 4) * BSTRIDE + 8 * j];
            }
#pragma unroll
            for (int i = 0; i < 4; i++)
#pragma unroll
                for (int j = 0; j < 8; j++)
                    MMA_TF32(acc[i][j], af[i], bf[j]);
        }
        __syncthreads();
    }

    // ---- epilogue ----
    float* outbase = MODE ? (float*)g_y : (float*)g_h;

    float bv[16];
    if (MODE == 0) {
#pragma unroll
        for (int j = 0; j < 8; j++) {
            float2 t = *(const float2*)(bias + e * FF + ntb + wn * 64 + 8 * j + lc * 2);
            bv[2 * j] = t.x; bv[2 * j + 1] = t.y;
        }
    }

#pragma unroll
    for (int i = 0; i < 4; i++) {
        const int mr0 = wm * 64 + 16 * i + lr;
        const int s0 = sslot[mr0];
        const int s1 = sslot[mr0 + 8];
#pragma unroll
        for (int j = 0; j < 8; j++) {
            const int n = ntb + wn * 64 + 8 * j + lc * 2;
            if (MODE == 0) {
                if (s0 >= 0) {
                    float2 v;
                    v.x = __uint_as_float(f2tf32(fgelu(acc[i][j][0] + bv[2 * j])));
                    v.y = __uint_as_float(f2tf32(fgelu(acc[i][j][1] + bv[2 * j + 1])));
                    *(float2*)(outbase + (size_t)s0 * OROW + n) = v;
                }
                if (s1 >= 0) {
                    float2 v;
                    v.x = __uint_as_float(f2tf32(fgelu(acc[i][j][2] + bv[2 * j])));
                    v.y = __uint_as_float(f2tf32(fgelu(acc[i][j][3] + bv[2 * j + 1])));
                    *(float2*)(outbase + (size_t)s1 * OROW + n) = v;
                }
            } else {
                if (s0 >= 0)
                    *(float2*)(outbase + (size_t)s0 * OROW + n) =
                        make_float2(acc[i][j][0], acc[i][j][1]);
                if (s1 >= 0)
                    *(float2*)(outbase + (size_t)s1 * OROW + n) =
                        make_float2(acc[i][j][2], acc[i][j][3]);
            }
        }
    }
}

// ---------------------------------------------------------------------------
// out[t] = p0[t] * (y[2t] + y[2t+1] + b2[e0] + b2[e1])
// ---------------------------------------------------------------------------
__global__ void k_combine(const float* __restrict__ b2, float* __restrict__ out) {
    int idx = blockIdx.x * blockDim.x + threadIdx.x;   // over TB*HD/4
    int tok = idx >> 8;       // HD/4 = 256
    int h4  = idx & 255;
    int e0 = g_eid[2 * tok], e1 = g_eid[2 * tok + 1];
    float p0 = g_p0[tok];
    float4 y0 = ((const float4*)g_y)[(size_t)(2 * tok) * 256 + h4];
    float4 y1 = ((const float4*)g_y)[(size_t)(2 * tok + 1) * 256 + h4];
    float4 c0 = *(const float4*)(b2 + e0 * HD + 4 * h4);
    float4 c1 = *(const float4*)(b2 + e1 * HD + 4 * h4);
    float4 o;
    o.x = p0 * (y0.x + y1.x + c0.x + c1.x);
    o.y = p0 * (y0.y + y1.y + c0.y + c1.y);
    o.z = p0 * (y0.z + y1.z + c0.z + c1.z);
    o.w = p0 * (y0.w + y1.w + c0.w + c1.w);
    ((float4*)out)[idx] = o;
}

// ---------------------------------------------------------------------------
extern "C" void kernel_launch(void* const* d_in, const int* in_sizes, int n_in,
                              void* d_out, int out_size) {
    const float* x  = (const float*)d_in[0];
    const float* Wr = (const float*)d_in[1];
    const float* br = (const float*)d_in[2];
    const float* W1 = (const float*)d_in[3];
    const float* b1 = (const float*)d_in[4];
    const float* W2 = (const float*)d_in[5];
    const float* b2 = (const float*)d_in[6];
    float* out = (float*)d_out;

    cudaFuncSetAttribute(k_gemm<0>, cudaFuncAttributeMaxDynamicSharedMemorySize, SMEM_SZ);
    cudaFuncSetAttribute(k_gemm<1>, cudaFuncAttributeMaxDynamicSharedMemorySize, SMEM_SZ);

    k_init<<<1, 32>>>();
    k_router<<<TB / 8, 256>>>(x, Wr, br);
    dim3 g1(FF / BN, TB / BM, NE);   // (32, 64, 8)
    k_gemm<0><<<g1, GT, SMEM_SZ>>>(W1, b1);
    dim3 g2(HD / BN, TB / BM, NE);   // (8, 64, 8)
    k_gemm<1><<<g2, GT, SMEM_SZ>>>(W2, nullptr);
    k_combine<<<TB * HD / 4 / 256, 256>>>(b2, out);
}